// round 13
// baseline (speedup 1.0000x reference)
#include <cuda_runtime.h>
#include <cuda_fp16.h>
#include <math.h>
#include <stdint.h>

#define BB 8
#define SS 2048
#define DD 512
#define MTOT (BB*SS)

__device__ __half g_xh[MTOT*DD];
__device__ __half g_Wth[3][DD*DD];
__device__ float  g_bias[3*DD];
__device__ __half g_QKV[3][MTOT*DD];
__device__ __half g_Vth[MTOT*DD];
__device__ __half g_Sc[(long long)BB*SS*SS];
__device__ float  g_rowsum[MTOT];

__device__ __forceinline__ uint32_t smem_u32(const void* p){
    uint32_t a;
    asm("{ .reg .u64 t; cvta.to.shared.u64 t, %1; cvt.u32.u64 %0, t; }" : "=r"(a) : "l"(p));
    return a;
}
__device__ __forceinline__ void cpa16(uint32_t dst, const void* src){
    asm volatile("cp.async.cg.shared.global [%0], [%1], 16;" :: "r"(dst), "l"(src));
}
__device__ __forceinline__ void cpa_commit(){ asm volatile("cp.async.commit_group;"); }
template<int N> __device__ __forceinline__ void cpa_wait(){
    asm volatile("cp.async.wait_group %0;" :: "n"(N));
}
__device__ __forceinline__ void ldm_x4(uint32_t* r, uint32_t addr){
    asm volatile("ldmatrix.sync.aligned.m8n8.x4.shared.b16 {%0,%1,%2,%3}, [%4];"
        : "=r"(r[0]), "=r"(r[1]), "=r"(r[2]), "=r"(r[3]) : "r"(addr));
}
__device__ __forceinline__ void mma16816(float* d, const uint32_t* a, uint32_t b0, uint32_t b1){
    asm volatile("mma.sync.aligned.m16n8k16.row.col.f32.f16.f16.f32 "
        "{%0,%1,%2,%3},{%4,%5,%6,%7},{%8,%9},{%0,%1,%2,%3};"
        : "+f"(d[0]), "+f"(d[1]), "+f"(d[2]), "+f"(d[3])
        : "r"(a[0]), "r"(a[1]), "r"(a[2]), "r"(a[3]), "r"(b0), "r"(b1));
}
__device__ __forceinline__ float ex2(float x){
    float r;
    asm("ex2.approx.ftz.f32 %0, %1;" : "=f"(r) : "f"(x));
    return r;
}
#define L2E 1.44269504f

// K-chunk 64: 128 rows x 128B data, pitch 144 (row bank-stride 36 -> conflict-free ldmatrix)
#define PITCH   144
#define MATB    (128*PITCH)      // 18432
#define STAGEB  (2*MATB)         // 36864
#define SMEM_G  (2*STAGEB)       // 73728

// 256 threads, 8 warps of 64x32, CTA tile 128x128, K-chunk 64, 2-stage, single sync.
// 1-term plain fp16: C = A * B^T
// EPI 2: Ch = fp16(D + bias[z])
// EPI 4: Ch = fp16(alpha*D), plus per-row sum of exp(Ch) atomicAdd'ed to rowsum
template<int EPI>
__global__ void __launch_bounds__(256, 2)
gemm_mma(const __half* __restrict__ Ah, const __half* __restrict__ Bh,
         const float* __restrict__ bias,
         __half* __restrict__ Ch, float* __restrict__ rowsum,
         int N, int K, float alpha,
         long long sA, long long sB, long long sC)
{
    extern __shared__ char smem[];
    const uint32_t sb = smem_u32(smem);
    const int tid = threadIdx.x;
    const int wid = tid >> 5, lane = tid & 31;
    const int wr = wid >> 2, wc = wid & 3;
    const int wm0 = wr * 64, wn0 = wc * 32;

    const int row0 = blockIdx.y << 7, col0 = blockIdx.x << 7;
    const long long zA = (long long)blockIdx.z * sA;
    const long long zB = (long long)blockIdx.z * sB;
    const long long zC = (long long)blockIdx.z * sC;
    const float* biasz = (EPI == 2) ? (bias + blockIdx.z * DD) : bias;

    const __half* gsrc[2] = { Ah + zA + (long long)row0 * K,
                              Bh + zB + (long long)col0 * K };

    const int lrow = tid >> 1;               // 0..127
    const int lu0  = (tid & 1) * 4;          // unit base 0 or 4

    float acc[4][4][4];
#pragma unroll
    for (int i = 0; i < 4; i++)
#pragma unroll
        for (int j = 0; j < 4; j++)
#pragma unroll
            for (int q = 0; q < 4; q++) acc[i][j][q] = 0.0f;

    const int NC = K >> 6;   // chunks of 64

    auto load_chunk = [&](int stage, int kc) {
        const uint32_t sdst = sb + stage * STAGEB;
#pragma unroll
        for (int m = 0; m < 2; m++) {
            const __half* g = gsrc[m] + kc * 64 + (long long)lrow * K;
            const uint32_t d = sdst + m * MATB + lrow * PITCH;
#pragma unroll
            for (int it = 0; it < 4; it++) {
                const int u = lu0 + it;
                cpa16(d + u * 16, g + u * 8);
            }
        }
    };

    load_chunk(0, 0);
    cpa_commit();

    for (int kc = 0; kc < NC; kc++) {
        const int s = kc & 1;
        cpa_wait<0>();
        __syncthreads();

        const uint32_t sAh = sb + s * STAGEB;
        const uint32_t sBh = sAh + MATB;
        const int lr = lane & 15;
        const int lc = (lane >> 4) * 16;

#pragma unroll
        for (int k16 = 0; k16 < 4; k16++) {
            const uint32_t kb = k16 * 32 + lc;
            uint32_t ah[4][4], bh[2][4];
#pragma unroll
            for (int i = 0; i < 4; i++)
                ldm_x4(ah[i], sAh + (uint32_t)(wm0 + i * 16 + lr) * PITCH + kb);
#pragma unroll
            for (int jj = 0; jj < 2; jj++)
                ldm_x4(bh[jj], sBh + (uint32_t)(wn0 + jj * 16 + lr) * PITCH + kb);
            if (k16 == 0 && kc + 1 < NC) {
                load_chunk(s ^ 1, kc + 1);
                cpa_commit();
            }
#pragma unroll
            for (int i = 0; i < 4; i++)
#pragma unroll
                for (int j = 0; j < 4; j++) {
                    const int jj = j >> 1, sel = j & 1;
                    mma16816(acc[i][j], ah[i], bh[jj][sel], bh[jj][sel + 2]);
                }
        }
    }

    const int er = lane >> 2;
    const int ec = (lane & 3) * 2;
    float esum[4][2];
#pragma unroll
    for (int i = 0; i < 4; i++) { esum[i][0] = 0.0f; esum[i][1] = 0.0f; }

#pragma unroll
    for (int i = 0; i < 4; i++) {
#pragma unroll
        for (int j = 0; j < 4; j++) {
            const int col = col0 + wn0 + j * 8 + ec;
#pragma unroll
            for (int half_m = 0; half_m < 2; half_m++) {
                const int row = row0 + wm0 + i * 16 + er + half_m * 8;
                const float d0 = acc[i][j][half_m * 2 + 0];
                const float d1 = acc[i][j][half_m * 2 + 1];
                if (EPI == 2) {
                    float f0 = d0 + biasz[col];
                    float f1 = d1 + biasz[col + 1];
                    *(__half2*)(Ch + zC + (long long)row * N + col) =
                        __halves2half2(__float2half_rn(f0), __float2half_rn(f1));
                } else {
                    __half h0 = __float2half_rn(d0 * alpha);
                    __half h1 = __float2half_rn(d1 * alpha);
                    *(__half2*)(Ch + zC + (long long)row * N + col) = __halves2half2(h0, h1);
                    esum[i][half_m] += ex2(__half2float(h0) * L2E) + ex2(__half2float(h1) * L2E);
                }
            }
        }
    }

    if (EPI == 4) {
        __syncthreads();
        float* red = (float*)smem;   // [128][4]
#pragma unroll
        for (int i = 0; i < 4; i++) {
#pragma unroll
            for (int half_m = 0; half_m < 2; half_m++) {
                float s = esum[i][half_m];
                s += __shfl_xor_sync(0xffffffffu, s, 1);
                s += __shfl_xor_sync(0xffffffffu, s, 2);
                if ((lane & 3) == 0)
                    red[(wm0 + i * 16 + half_m * 8 + er) * 4 + wc] = s;
            }
        }
        __syncthreads();
        if (tid < 128) {
            float s = red[tid*4+0] + red[tid*4+1] + red[tid*4+2] + red[tid*4+3];
            atomicAdd(&rowsum[(long long)blockIdx.z * SS + row0 + tid], s);
        }
    }
}

// fused softmax+PV: out = (exp(S) @ V^T) / rowsum, K-chunk 64
__global__ void __launch_bounds__(256, 2)
gemm_pv(const __half* __restrict__ Sc, const float* __restrict__ rowsum,
        const __half* __restrict__ Vt, float* __restrict__ out)
{
    extern __shared__ char smem[];
    const uint32_t sb = smem_u32(smem);
    const int tid = threadIdx.x;
    const int wid = tid >> 5, lane = tid & 31;
    const int wr = wid >> 2, wc = wid & 3;
    const int wm0 = wr * 64, wn0 = wc * 32;

    const int col0 = blockIdx.x << 7, row0 = blockIdx.y << 7, b = blockIdx.z;
    const __half* A  = Sc + ((long long)(b * SS + row0)) * SS;
    const __half* Bv = Vt + ((long long)(b * DD + col0)) * SS;
    float* C = out + ((long long)(b * SS + row0)) * DD;

    // A: 2 threads per row, each covers 32 halves (64B = 4 uint4)
    const int arow = tid >> 1;
    const int ah32 = (tid & 1) * 32;          // half offset within chunk
    // B loader: 2 threads per row, 4 units each
    const int brow = tid >> 1;
    const int bu0  = (tid & 1) * 4;

    uint4 areg[4];
    {
        const __half* p = A + (long long)arow * SS + ah32;
#pragma unroll
        for (int u = 0; u < 4; u++) areg[u] = *(const uint4*)(p + u * 8);
        const __half* g = Bv + (long long)brow * SS;
        const uint32_t d = sb + MATB + brow * PITCH;
#pragma unroll
        for (int it = 0; it < 4; it++) {
            const int u = bu0 + it;
            cpa16(d + u * 16, g + u * 8);
        }
        cpa_commit();
    }

    float acc[4][4][4];
#pragma unroll
    for (int i = 0; i < 4; i++)
#pragma unroll
        for (int j = 0; j < 4; j++)
#pragma unroll
            for (int q = 0; q < 4; q++) acc[i][j][q] = 0.0f;

    const int NC = SS >> 6;   // 32

    for (int kc = 0; kc < NC; kc++) {
        const int s = kc & 1;
        // convert prefetched scores -> exp, STS into stage s A tile
        {
            char* d = smem + s * STAGEB + arow * PITCH + ah32 * 2;
#pragma unroll
            for (int u = 0; u < 4; u++) {
                const __half2* h2 = (const __half2*)&areg[u];
                __half2 o[4];
#pragma unroll
                for (int j = 0; j < 4; j++) {
                    float2 f = __half22float2(h2[j]);
                    f.x = ex2(f.x * L2E);
                    f.y = ex2(f.y * L2E);
                    o[j] = __float22half2_rn(f);
                }
                *(uint4*)(d + u * 16) = *(uint4*)&o[0];
            }
        }
        cpa_wait<0>();
        __syncthreads();

        const uint32_t sA = sb + s * STAGEB;
        const uint32_t sB = sA + MATB;
        const int lr = lane & 15;
        const int lc = (lane >> 4) * 16;

#pragma unroll
        for (int k16 = 0; k16 < 4; k16++) {
            const uint32_t kb = k16 * 32 + lc;
            uint32_t ahf[4][4], bhf[2][4];
#pragma unroll
            for (int i = 0; i < 4; i++)
                ldm_x4(ahf[i], sA + (uint32_t)(wm0 + i * 16 + lr) * PITCH + kb);
#pragma unroll
            for (int jj = 0; jj < 2; jj++)
                ldm_x4(bhf[jj], sB + (uint32_t)(wn0 + jj * 16 + lr) * PITCH + kb);

            if (k16 == 0 && kc + 1 < NC) {
                const __half* p = A + (long long)arow * SS + (kc + 1) * 64 + ah32;
#pragma unroll
                for (int u = 0; u < 4; u++) areg[u] = *(const uint4*)(p + u * 8);
                const __half* g = Bv + (long long)brow * SS + (kc + 1) * 64;
                const uint32_t d = sb + (s ^ 1) * STAGEB + MATB + brow * PITCH;
#pragma unroll
                for (int it = 0; it < 4; it++) {
                    const int u = bu0 + it;
                    cpa16(d + u * 16, g + u * 8);
                }
                cpa_commit();
            }
#pragma unroll
            for (int i = 0; i < 4; i++)
#pragma unroll
                for (int j = 0; j < 4; j++) {
                    const int jj = j >> 1, sel = j & 1;
                    mma16816(acc[i][j], ahf[i], bhf[jj][sel], bhf[jj][sel + 2]);
                }
        }
    }

    const int er = lane >> 2;
    const int ec = (lane & 3) * 2;
#pragma unroll
    for (int i = 0; i < 4; i++) {
#pragma unroll
        for (int half_m = 0; half_m < 2; half_m++) {
            const int lrow = wm0 + i * 16 + er + half_m * 8;
            const float inv = 1.0f / rowsum[b * SS + row0 + lrow];
#pragma unroll
            for (int j = 0; j < 4; j++) {
                const int col = col0 + wn0 + j * 8 + ec;
                float2 v;
                v.x = acc[i][j][half_m * 2 + 0] * inv;
                v.y = acc[i][j][half_m * 2 + 1] * inv;
                *(float2*)(C + (long long)lrow * DD + col) = v;
            }
        }
    }
}

__global__ void __launch_bounds__(256)
cvt_f32_f16(const float* __restrict__ s, __half* __restrict__ h, int n4)
{
    int i = blockIdx.x * 256 + threadIdx.x;
    if (i >= n4) return;
    float4 v = ((const float4*)s)[i];
    *(__half2*)(h + 4*i)     = __halves2half2(__float2half_rn(v.x), __float2half_rn(v.y));
    *(__half2*)(h + 4*i + 2) = __halves2half2(__float2half_rn(v.z), __float2half_rn(v.w));
}

// fp32 [R,C] -> fp16 [C,R]
__global__ void __launch_bounds__(256)
transpose_cvt(const float* __restrict__ src, __half* __restrict__ dst, int R, int C)
{
    __shared__ float t[32][33];
    const int c0 = blockIdx.x * 32, r0 = blockIdx.y * 32;
    const int tx = threadIdx.x, ty = threadIdx.y;
#pragma unroll
    for (int k = 0; k < 4; k++)
        t[ty + 8*k][tx] = src[(long long)(r0 + ty + 8*k) * C + c0 + tx];
    __syncthreads();
#pragma unroll
    for (int k = 0; k < 4; k++)
        dst[(long long)(c0 + ty + 8*k) * R + r0 + tx] = __float2half_rn(t[tx][ty + 8*k]);
}

// fp16 [R,C] -> fp16 [C,R] per batch
__global__ void __launch_bounds__(256)
transpose_h16(const __half* __restrict__ src, __half* __restrict__ dst,
              int R, int C, long long sS, long long sD)
{
    __shared__ __half t[32][34];
    const __half* S = src + (long long)blockIdx.z * sS;
    __half* D = dst + (long long)blockIdx.z * sD;
    const int c0 = blockIdx.x * 32, r0 = blockIdx.y * 32;
    const int tx = threadIdx.x, ty = threadIdx.y;
#pragma unroll
    for (int k = 0; k < 4; k++)
        t[ty + 8*k][tx] = S[(long long)(r0 + ty + 8*k) * C + c0 + tx];
    __syncthreads();
#pragma unroll
    for (int k = 0; k < 4; k++)
        D[(long long)(c0 + ty + 8*k) * R + r0 + tx] = t[tx][ty + 8*k];
}

extern "C" void kernel_launch(void* const* d_in, const int* in_sizes, int n_in,
                              void* d_out, int out_size)
{
    (void)in_sizes; (void)n_in; (void)out_size;
    const float* x  = (const float*)d_in[0];
    const float* Wq = (const float*)d_in[1];
    const float* bq = (const float*)d_in[2];
    const float* Wk = (const float*)d_in[3];
    const float* bk = (const float*)d_in[4];
    const float* Wv = (const float*)d_in[5];
    const float* bv = (const float*)d_in[6];
    float* out = (float*)d_out;

    __half *xh, *Wth, *QKV, *Vth, *Sc;
    float *bias, *rowsum;
    cudaGetSymbolAddress((void**)&xh,     g_xh);
    cudaGetSymbolAddress((void**)&Wth,    g_Wth);
    cudaGetSymbolAddress((void**)&bias,   g_bias);
    cudaGetSymbolAddress((void**)&QKV,    g_QKV);
    cudaGetSymbolAddress((void**)&Vth,    g_Vth);
    cudaGetSymbolAddress((void**)&Sc,     g_Sc);
    cudaGetSymbolAddress((void**)&rowsum, g_rowsum);

    cudaFuncSetAttribute((const void*)gemm_mma<2>, cudaFuncAttributeMaxDynamicSharedMemorySize, SMEM_G);
    cudaFuncSetAttribute((const void*)gemm_mma<4>, cudaFuncAttributeMaxDynamicSharedMemorySize, SMEM_G);
    cudaFuncSetAttribute((const void*)gemm_pv,     cudaFuncAttributeMaxDynamicSharedMemorySize, SMEM_G);

    const float scale = 1.0f / sqrtf((float)DD);
    __half* Qh = QKV + 0 * (long long)MTOT * DD;
    __half* Kh = QKV + 1 * (long long)MTOT * DD;
    __half* Vh = QKV + 2 * (long long)MTOT * DD;

    // biases into one device array (async D2D, graph-legal)
    cudaMemcpyAsync(bias + 0*DD, bq, DD * sizeof(float), cudaMemcpyDeviceToDevice);
    cudaMemcpyAsync(bias + 1*DD, bk, DD * sizeof(float), cudaMemcpyDeviceToDevice);
    cudaMemcpyAsync(bias + 2*DD, bv, DD * sizeof(float), cudaMemcpyDeviceToDevice);

    {
        dim3 tb(32, 8), tg(DD/32, DD/32);
        transpose_cvt<<<tg, tb>>>(Wq, Wth + 0*DD*DD, DD, DD);
        transpose_cvt<<<tg, tb>>>(Wk, Wth + 1*DD*DD, DD, DD);
        transpose_cvt<<<tg, tb>>>(Wv, Wth + 2*DD*DD, DD, DD);
    }
    {
        int n4 = MTOT * DD / 4;
        cvt_f32_f16<<<(n4 + 255) / 256, 256>>>(x, xh, n4);
    }
    // merged Q/K/V projections: z = 0..2
    {
        dim3 g(DD/128, MTOT/128, 3);
        gemm_mma<2><<<g, 256, SMEM_G>>>(xh, Wth, bias, QKV, nullptr,
                                        DD, DD, 1.0f,
                                        0, (long long)DD*DD, (long long)MTOT*DD);
    }
    {
        dim3 tb(32, 8), tg(DD/32, SS/32, BB);
        transpose_h16<<<tg, tb>>>(Vh, Vth, SS, DD, (long long)SS*DD, (long long)DD*SS);
    }
    cudaMemsetAsync(rowsum, 0, MTOT * sizeof(float));
    {
        dim3 g(SS/128, SS/128, BB);
        gemm_mma<4><<<g, 256, SMEM_G>>>(Qh, Kh, nullptr, Sc, rowsum,
                                        SS, DD, scale,
                                        (long long)SS*DD, (long long)SS*DD,
                                        (long long)SS*SS);
    }
    {
        dim3 g(DD/128, SS/128, BB);
        gemm_pv<<<g, 256, SMEM_G>>>(Sc, rowsum, Vth, out);
    }
}

// round 14
// speedup vs baseline: 1.1488x; 1.1488x over previous
#include <cuda_runtime.h>
#include <cuda_fp16.h>
#include <math.h>
#include <stdint.h>

#define BB 8
#define SS 2048
#define DD 512
#define MTOT (BB*SS)

__device__ __half g_xh[MTOT*DD];
__device__ __half g_Wth[3][DD*DD];
__device__ float  g_bias[3*DD];
__device__ __half g_QKV[3][MTOT*DD];
__device__ __half g_Vth[MTOT*DD];
__device__ __half g_Sc[(long long)BB*SS*SS];
__device__ float  g_rowsum[MTOT];

__device__ __forceinline__ uint32_t smem_u32(const void* p){
    uint32_t a;
    asm("{ .reg .u64 t; cvta.to.shared.u64 t, %1; cvt.u32.u64 %0, t; }" : "=r"(a) : "l"(p));
    return a;
}
__device__ __forceinline__ void cpa16(uint32_t dst, const void* src){
    asm volatile("cp.async.cg.shared.global [%0], [%1], 16;" :: "r"(dst), "l"(src));
}
__device__ __forceinline__ void cpa_commit(){ asm volatile("cp.async.commit_group;"); }
template<int N> __device__ __forceinline__ void cpa_wait(){
    asm volatile("cp.async.wait_group %0;" :: "n"(N));
}
__device__ __forceinline__ void ldm_x4(uint32_t* r, uint32_t addr){
    asm volatile("ldmatrix.sync.aligned.m8n8.x4.shared.b16 {%0,%1,%2,%3}, [%4];"
        : "=r"(r[0]), "=r"(r[1]), "=r"(r[2]), "=r"(r[3]) : "r"(addr));
}
__device__ __forceinline__ void mma16816(float* d, const uint32_t* a, uint32_t b0, uint32_t b1){
    asm volatile("mma.sync.aligned.m16n8k16.row.col.f32.f16.f16.f32 "
        "{%0,%1,%2,%3},{%4,%5,%6,%7},{%8,%9},{%0,%1,%2,%3};"
        : "+f"(d[0]), "+f"(d[1]), "+f"(d[2]), "+f"(d[3])
        : "r"(a[0]), "r"(a[1]), "r"(a[2]), "r"(a[3]), "r"(b0), "r"(b1));
}
__device__ __forceinline__ float ex2(float x){
    float r;
    asm("ex2.approx.ftz.f32 %0, %1;" : "=f"(r) : "f"(x));
    return r;
}
#define L2E 1.44269504f

#define PITCH   80
#define MATB    (128*PITCH)
#define STAGEB  (2*MATB)
#define SMEM_G  (2*STAGEB)      // 40960

// 256 threads, 8 warps of 64x32, CTA tile 128x128, K-chunk 32, 2-stage, single sync.
// 1-term plain fp16: C = A * B^T
// EPI 2: Ch = fp16(D + bias[z])
// EPI 4: Ch = fp16(alpha*D), plus per-row sum of exp(Ch) atomicAdd'ed to rowsum
template<int EPI>
__global__ void __launch_bounds__(256, 2)
gemm_mma(const __half* __restrict__ Ah, const __half* __restrict__ Bh,
         const float* __restrict__ bias,
         __half* __restrict__ Ch, float* __restrict__ rowsum,
         int N, int K, float alpha,
         long long sA, long long sB, long long sC)
{
    extern __shared__ char smem[];
    const uint32_t sb = smem_u32(smem);
    const int tid = threadIdx.x;
    const int wid = tid >> 5, lane = tid & 31;
    const int wr = wid >> 2, wc = wid & 3;
    const int wm0 = wr * 64, wn0 = wc * 32;

    const int row0 = blockIdx.y << 7, col0 = blockIdx.x << 7;
    const long long zA = (long long)blockIdx.z * sA;
    const long long zB = (long long)blockIdx.z * sB;
    const long long zC = (long long)blockIdx.z * sC;
    const float* biasz = (EPI == 2) ? (bias + blockIdx.z * DD) : bias;

    const __half* gsrc[2] = { Ah + zA + (long long)row0 * K,
                              Bh + zB + (long long)col0 * K };

    const int lrow0 = tid >> 2;
    const int lu    = tid & 3;

    float acc[4][4][4];
#pragma unroll
    for (int i = 0; i < 4; i++)
#pragma unroll
        for (int j = 0; j < 4; j++)
#pragma unroll
            for (int q = 0; q < 4; q++) acc[i][j][q] = 0.0f;

    const int NC = K >> 5;

    auto load_chunk = [&](int stage, int kc) {
        const uint32_t sdst = sb + stage * STAGEB;
#pragma unroll
        for (int m = 0; m < 2; m++) {
            const __half* g = gsrc[m] + kc * 32;
#pragma unroll
            for (int it = 0; it < 2; it++) {
                const int row = lrow0 + it * 64;
                cpa16(sdst + m * MATB + row * PITCH + lu * 16,
                      g + (long long)row * K + lu * 8);
            }
        }
    };

    load_chunk(0, 0);
    cpa_commit();

    for (int kc = 0; kc < NC; kc++) {
        const int s = kc & 1;
        cpa_wait<0>();
        __syncthreads();

        const uint32_t sAh = sb + s * STAGEB;
        const uint32_t sBh = sAh + MATB;
        const int lr = lane & 15;
        const int lc = (lane >> 4) * 16;

#pragma unroll
        for (int k16 = 0; k16 < 2; k16++) {
            const uint32_t kb = k16 * 32 + lc;
            uint32_t ah[4][4], bh[2][4];
#pragma unroll
            for (int i = 0; i < 4; i++)
                ldm_x4(ah[i], sAh + (uint32_t)(wm0 + i * 16 + lr) * PITCH + kb);
#pragma unroll
            for (int jj = 0; jj < 2; jj++)
                ldm_x4(bh[jj], sBh + (uint32_t)(wn0 + jj * 16 + lr) * PITCH + kb);
            if (k16 == 0 && kc + 1 < NC) {
                load_chunk(s ^ 1, kc + 1);
                cpa_commit();
            }
#pragma unroll
            for (int i = 0; i < 4; i++)
#pragma unroll
                for (int j = 0; j < 4; j++) {
                    const int jj = j >> 1, sel = j & 1;
                    mma16816(acc[i][j], ah[i], bh[jj][sel], bh[jj][sel + 2]);
                }
        }
    }

    const int er = lane >> 2;
    const int ec = (lane & 3) * 2;
    float esum[4][2];
#pragma unroll
    for (int i = 0; i < 4; i++) { esum[i][0] = 0.0f; esum[i][1] = 0.0f; }

#pragma unroll
    for (int i = 0; i < 4; i++) {
#pragma unroll
        for (int j = 0; j < 4; j++) {
            const int col = col0 + wn0 + j * 8 + ec;
#pragma unroll
            for (int half_m = 0; half_m < 2; half_m++) {
                const int row = row0 + wm0 + i * 16 + er + half_m * 8;
                const float d0 = acc[i][j][half_m * 2 + 0];
                const float d1 = acc[i][j][half_m * 2 + 1];
                if (EPI == 2) {
                    float f0 = d0 + biasz[col];
                    float f1 = d1 + biasz[col + 1];
                    *(__half2*)(Ch + zC + (long long)row * N + col) =
                        __halves2half2(__float2half_rn(f0), __float2half_rn(f1));
                } else {
                    __half h0 = __float2half_rn(d0 * alpha);
                    __half h1 = __float2half_rn(d1 * alpha);
                    *(__half2*)(Ch + zC + (long long)row * N + col) = __halves2half2(h0, h1);
                    esum[i][half_m] += ex2(__half2float(h0) * L2E) + ex2(__half2float(h1) * L2E);
                }
            }
        }
    }

    if (EPI == 4) {
        __syncthreads();
        float* red = (float*)smem;   // [128][4]
#pragma unroll
        for (int i = 0; i < 4; i++) {
#pragma unroll
            for (int half_m = 0; half_m < 2; half_m++) {
                float s = esum[i][half_m];
                s += __shfl_xor_sync(0xffffffffu, s, 1);
                s += __shfl_xor_sync(0xffffffffu, s, 2);
                if ((lane & 3) == 0)
                    red[(wm0 + i * 16 + half_m * 8 + er) * 4 + wc] = s;
            }
        }
        __syncthreads();
        if (tid < 128) {
            float s = red[tid*4+0] + red[tid*4+1] + red[tid*4+2] + red[tid*4+3];
            atomicAdd(&rowsum[(long long)blockIdx.z * SS + row0 + tid], s);
        }
    }
}

// fused softmax+PV: out = (exp(S) @ V^T) / rowsum
__global__ void __launch_bounds__(256, 2)
gemm_pv(const __half* __restrict__ Sc, const float* __restrict__ rowsum,
        const __half* __restrict__ Vt, float* __restrict__ out)
{
    extern __shared__ char smem[];
    const uint32_t sb = smem_u32(smem);
    const int tid = threadIdx.x;
    const int wid = tid >> 5, lane = tid & 31;
    const int wr = wid >> 2, wc = wid & 3;
    const int wm0 = wr * 64, wn0 = wc * 32;

    const int col0 = blockIdx.x << 7, row0 = blockIdx.y << 7, b = blockIdx.z;
    const __half* A  = Sc + ((long long)(b * SS + row0)) * SS;
    const __half* Bv = Vt + ((long long)(b * DD + col0)) * SS;
    float* C = out + ((long long)(b * SS + row0)) * DD;

    const int arow  = tid >> 1;
    const int acolh = (tid & 1) * 16;
    const int brow0 = tid >> 2, bu = tid & 3;

    uint4 areg0, areg1;
    {
        const __half* p = A + (long long)arow * SS + acolh;
        areg0 = *(const uint4*)p;
        areg1 = *(const uint4*)(p + 8);
#pragma unroll
        for (int it = 0; it < 2; it++) {
            const int r = brow0 + it * 64;
            cpa16(sb + MATB + r * PITCH + bu * 16, Bv + (long long)r * SS + bu * 8);
        }
        cpa_commit();
    }

    float acc[4][4][4];
#pragma unroll
    for (int i = 0; i < 4; i++)
#pragma unroll
        for (int j = 0; j < 4; j++)
#pragma unroll
            for (int q = 0; q < 4; q++) acc[i][j][q] = 0.0f;

    const int NC = SS >> 5;

    for (int kc = 0; kc < NC; kc++) {
        const int s = kc & 1;
        {
            char* d = smem + s * STAGEB + arow * PITCH + acolh * 2;
            __half2 o[8];
            const __half2* h2a = (const __half2*)&areg0;
            const __half2* h2b = (const __half2*)&areg1;
#pragma unroll
            for (int j = 0; j < 4; j++) {
                float2 f = __half22float2(h2a[j]);
                f.x = ex2(f.x * L2E);
                f.y = ex2(f.y * L2E);
                o[j] = __float22half2_rn(f);
            }
#pragma unroll
            for (int j = 0; j < 4; j++) {
                float2 f = __half22float2(h2b[j]);
                f.x = ex2(f.x * L2E);
                f.y = ex2(f.y * L2E);
                o[4 + j] = __float22half2_rn(f);
            }
            *(uint4*)d        = *(uint4*)&o[0];
            *(uint4*)(d + 16) = *(uint4*)&o[4];
        }
        cpa_wait<0>();
        __syncthreads();

        const uint32_t sA = sb + s * STAGEB;
        const uint32_t sB = sA + MATB;
        const int lr = lane & 15;
        const int lc = (lane >> 4) * 16;

#pragma unroll
        for (int k16 = 0; k16 < 2; k16++) {
            const uint32_t kb = k16 * 32 + lc;
            uint32_t ah[4][4], bh[2][4];
#pragma unroll
            for (int i = 0; i < 4; i++)
                ldm_x4(ah[i], sA + (uint32_t)(wm0 + i * 16 + lr) * PITCH + kb);
#pragma unroll
            for (int jj = 0; jj < 2; jj++)
                ldm_x4(bh[jj], sB + (uint32_t)(wn0 + jj * 16 + lr) * PITCH + kb);

            if (k16 == 0 && kc + 1 < NC) {
                const __half* p = A + (long long)arow * SS + (kc + 1) * 32 + acolh;
                areg0 = *(const uint4*)p;
                areg1 = *(const uint4*)(p + 8);
#pragma unroll
                for (int it = 0; it < 2; it++) {
                    const int r = brow0 + it * 64;
                    cpa16(sb + (s ^ 1) * STAGEB + MATB + r * PITCH + bu * 16,
                          Bv + (long long)r * SS + (kc + 1) * 32 + bu * 8);
                }
                cpa_commit();
            }
#pragma unroll
            for (int i = 0; i < 4; i++)
#pragma unroll
                for (int j = 0; j < 4; j++) {
                    const int jj = j >> 1, sel = j & 1;
                    mma16816(acc[i][j], ah[i], bh[jj][sel], bh[jj][sel + 2]);
                }
        }
    }

    const int er = lane >> 2;
    const int ec = (lane & 3) * 2;
#pragma unroll
    for (int i = 0; i < 4; i++) {
#pragma unroll
        for (int half_m = 0; half_m < 2; half_m++) {
            const int lrow = wm0 + i * 16 + er + half_m * 8;
            const float inv = 1.0f / rowsum[b * SS + row0 + lrow];
#pragma unroll
            for (int j = 0; j < 4; j++) {
                const int col = col0 + wn0 + j * 8 + ec;
                float2 v;
                v.x = acc[i][j][half_m * 2 + 0] * inv;
                v.y = acc[i][j][half_m * 2 + 1] * inv;
                *(float2*)(C + (long long)lrow * DD + col) = v;
            }
        }
    }
}

__global__ void __launch_bounds__(256)
cvt_f32_f16(const float* __restrict__ s, __half* __restrict__ h, int n4)
{
    int i = blockIdx.x * 256 + threadIdx.x;
    if (i >= n4) return;
    float4 v = ((const float4*)s)[i];
    *(__half2*)(h + 4*i)     = __halves2half2(__float2half_rn(v.x), __float2half_rn(v.y));
    *(__half2*)(h + 4*i + 2) = __halves2half2(__float2half_rn(v.z), __float2half_rn(v.w));
}

// fp32 [R,C] -> fp16 [C,R]
__global__ void __launch_bounds__(256)
transpose_cvt(const float* __restrict__ src, __half* __restrict__ dst, int R, int C)
{
    __shared__ float t[32][33];
    const int c0 = blockIdx.x * 32, r0 = blockIdx.y * 32;
    const int tx = threadIdx.x, ty = threadIdx.y;
#pragma unroll
    for (int k = 0; k < 4; k++)
        t[ty + 8*k][tx] = src[(long long)(r0 + ty + 8*k) * C + c0 + tx];
    __syncthreads();
#pragma unroll
    for (int k = 0; k < 4; k++)
        dst[(long long)(c0 + ty + 8*k) * R + r0 + tx] = __float2half_rn(t[tx][ty + 8*k]);
}

// fp16 [R,C] -> fp16 [C,R] per batch
__global__ void __launch_bounds__(256)
transpose_h16(const __half* __restrict__ src, __half* __restrict__ dst,
              int R, int C, long long sS, long long sD)
{
    __shared__ __half t[32][34];
    const __half* S = src + (long long)blockIdx.z * sS;
    __half* D = dst + (long long)blockIdx.z * sD;
    const int c0 = blockIdx.x * 32, r0 = blockIdx.y * 32;
    const int tx = threadIdx.x, ty = threadIdx.y;
#pragma unroll
    for (int k = 0; k < 4; k++)
        t[ty + 8*k][tx] = S[(long long)(r0 + ty + 8*k) * C + c0 + tx];
    __syncthreads();
#pragma unroll
    for (int k = 0; k < 4; k++)
        D[(long long)(c0 + ty + 8*k) * R + r0 + tx] = t[tx][ty + 8*k];
}

extern "C" void kernel_launch(void* const* d_in, const int* in_sizes, int n_in,
                              void* d_out, int out_size)
{
    (void)in_sizes; (void)n_in; (void)out_size;
    const float* x  = (const float*)d_in[0];
    const float* Wq = (const float*)d_in[1];
    const float* bq = (const float*)d_in[2];
    const float* Wk = (const float*)d_in[3];
    const float* bk = (const float*)d_in[4];
    const float* Wv = (const float*)d_in[5];
    const float* bv = (const float*)d_in[6];
    float* out = (float*)d_out;

    __half *xh, *Wth, *QKV, *Vth, *Sc;
    float *bias, *rowsum;
    cudaGetSymbolAddress((void**)&xh,     g_xh);
    cudaGetSymbolAddress((void**)&Wth,    g_Wth);
    cudaGetSymbolAddress((void**)&bias,   g_bias);
    cudaGetSymbolAddress((void**)&QKV,    g_QKV);
    cudaGetSymbolAddress((void**)&Vth,    g_Vth);
    cudaGetSymbolAddress((void**)&Sc,     g_Sc);
    cudaGetSymbolAddress((void**)&rowsum, g_rowsum);

    cudaFuncSetAttribute((const void*)gemm_mma<2>, cudaFuncAttributeMaxDynamicSharedMemorySize, SMEM_G);
    cudaFuncSetAttribute((const void*)gemm_mma<4>, cudaFuncAttributeMaxDynamicSharedMemorySize, SMEM_G);
    cudaFuncSetAttribute((const void*)gemm_pv,     cudaFuncAttributeMaxDynamicSharedMemorySize, SMEM_G);

    const float scale = 1.0f / sqrtf((float)DD);
    __half* Qh = QKV + 0 * (long long)MTOT * DD;
    __half* Kh = QKV + 1 * (long long)MTOT * DD;
    __half* Vh = QKV + 2 * (long long)MTOT * DD;

    cudaMemcpyAsync(bias + 0*DD, bq, DD * sizeof(float), cudaMemcpyDeviceToDevice);
    cudaMemcpyAsync(bias + 1*DD, bk, DD * sizeof(float), cudaMemcpyDeviceToDevice);
    cudaMemcpyAsync(bias + 2*DD, bv, DD * sizeof(float), cudaMemcpyDeviceToDevice);

    {
        dim3 tb(32, 8), tg(DD/32, DD/32);
        transpose_cvt<<<tg, tb>>>(Wq, Wth + 0*DD*DD, DD, DD);
        transpose_cvt<<<tg, tb>>>(Wk, Wth + 1*DD*DD, DD, DD);
        transpose_cvt<<<tg, tb>>>(Wv, Wth + 2*DD*DD, DD, DD);
    }
    {
        int n4 = MTOT * DD / 4;
        cvt_f32_f16<<<(n4 + 255) / 256, 256>>>(x, xh, n4);
    }
    // merged Q/K/V projections: z = 0..2
    {
        dim3 g(DD/128, MTOT/128, 3);
        gemm_mma<2><<<g, 256, SMEM_G>>>(xh, Wth, bias, QKV, nullptr,
                                        DD, DD, 1.0f,
                                        0, (long long)DD*DD, (long long)MTOT*DD);
    }
    {
        dim3 tb(32, 8), tg(DD/32, SS/32, BB);
        transpose_h16<<<tg, tb>>>(Vh, Vth, SS, DD, (long long)SS*DD, (long long)DD*SS);
    }
    cudaMemsetAsync(rowsum, 0, MTOT * sizeof(float));
    {
        dim3 g(SS/128, SS/128, BB);
        gemm_mma<4><<<g, 256, SMEM_G>>>(Qh, Kh, nullptr, Sc, rowsum,
                                        SS, DD, scale,
                                        (long long)SS*DD, (long long)SS*DD,
                                        (long long)SS*SS);
    }
    {
        dim3 g(DD/128, SS/128, BB);
        gemm_pv<<<g, 256, SMEM_G>>>(Sc, rowsum, Vth, out);
    }
}

// round 15
// speedup vs baseline: 1.1847x; 1.0312x over previous
#include <cuda_runtime.h>
#include <cuda_fp16.h>
#include <math.h>
#include <stdint.h>

#define BB 8
#define SS 2048
#define DD 512
#define MTOT (BB*SS)

__device__ __half g_xh[MTOT*DD];
__device__ __half g_Wth[3][DD*DD];
__device__ float  g_bias[3*DD];
__device__ __half g_QKV[3][MTOT*DD];
__device__ __half g_Vth[MTOT*DD];
__device__ __half g_Sc[(long long)BB*SS*SS];
__device__ float  g_rowsum[MTOT];

__device__ __forceinline__ uint32_t smem_u32(const void* p){
    uint32_t a;
    asm("{ .reg .u64 t; cvta.to.shared.u64 t, %1; cvt.u32.u64 %0, t; }" : "=r"(a) : "l"(p));
    return a;
}
__device__ __forceinline__ void cpa16(uint32_t dst, const void* src){
    asm volatile("cp.async.cg.shared.global [%0], [%1], 16;" :: "r"(dst), "l"(src));
}
__device__ __forceinline__ void cpa_commit(){ asm volatile("cp.async.commit_group;"); }
template<int N> __device__ __forceinline__ void cpa_wait(){
    asm volatile("cp.async.wait_group %0;" :: "n"(N));
}
__device__ __forceinline__ void ldm_x4(uint32_t* r, uint32_t addr){
    asm volatile("ldmatrix.sync.aligned.m8n8.x4.shared.b16 {%0,%1,%2,%3}, [%4];"
        : "=r"(r[0]), "=r"(r[1]), "=r"(r[2]), "=r"(r[3]) : "r"(addr));
}
__device__ __forceinline__ void mma16816(float* d, const uint32_t* a, uint32_t b0, uint32_t b1){
    asm volatile("mma.sync.aligned.m16n8k16.row.col.f32.f16.f16.f32 "
        "{%0,%1,%2,%3},{%4,%5,%6,%7},{%8,%9},{%0,%1,%2,%3};"
        : "+f"(d[0]), "+f"(d[1]), "+f"(d[2]), "+f"(d[3])
        : "r"(a[0]), "r"(a[1]), "r"(a[2]), "r"(a[3]), "r"(b0), "r"(b1));
}
__device__ __forceinline__ float ex2(float x){
    float r;
    asm("ex2.approx.ftz.f32 %0, %1;" : "=f"(r) : "f"(x));
    return r;
}
#define L2E 1.44269504f

#define PITCH   80
#define MATB    (128*PITCH)
#define STAGEB  (2*MATB)        // A + B per stage
#define SMEM_G  (3*STAGEB)      // 61440, 3-stage

// 256 threads, 8 warps of 64x32, CTA tile 128x128, K-chunk 32, 3-stage, single sync.
// 1-term plain fp16: C = A * B^T
// EPI 2: Ch = fp16(D + bias[z])
// EPI 4: Ch = fp16(alpha*D), plus per-row sum of exp(Ch) atomicAdd'ed to rowsum
template<int EPI>
__global__ void __launch_bounds__(256, 2)
gemm_mma(const __half* __restrict__ Ah, const __half* __restrict__ Bh,
         const float* __restrict__ bias,
         __half* __restrict__ Ch, float* __restrict__ rowsum,
         int N, int K, float alpha,
         long long sA, long long sB, long long sC)
{
    extern __shared__ char smem[];
    const uint32_t sb = smem_u32(smem);
    const int tid = threadIdx.x;
    const int wid = tid >> 5, lane = tid & 31;
    const int wr = wid >> 2, wc = wid & 3;
    const int wm0 = wr * 64, wn0 = wc * 32;

    const int row0 = blockIdx.y << 7, col0 = blockIdx.x << 7;
    const long long zA = (long long)blockIdx.z * sA;
    const long long zB = (long long)blockIdx.z * sB;
    const long long zC = (long long)blockIdx.z * sC;
    const float* biasz = (EPI == 2) ? (bias + blockIdx.z * DD) : bias;

    const __half* gsrc[2] = { Ah + zA + (long long)row0 * K,
                              Bh + zB + (long long)col0 * K };

    const int lrow0 = tid >> 2;
    const int lu    = tid & 3;

    float acc[4][4][4];
#pragma unroll
    for (int i = 0; i < 4; i++)
#pragma unroll
        for (int j = 0; j < 4; j++)
#pragma unroll
            for (int q = 0; q < 4; q++) acc[i][j][q] = 0.0f;

    const int NC = K >> 5;

    auto load_chunk = [&](int stage, int kc) {
        const uint32_t sdst = sb + stage * STAGEB;
#pragma unroll
        for (int m = 0; m < 2; m++) {
            const __half* g = gsrc[m] + kc * 32;
#pragma unroll
            for (int it = 0; it < 2; it++) {
                const int row = lrow0 + it * 64;
                cpa16(sdst + m * MATB + row * PITCH + lu * 16,
                      g + (long long)row * K + lu * 8);
            }
        }
    };

    // prologue: 2 chunks in flight
    load_chunk(0, 0);
    cpa_commit();
    load_chunk(1, 1);        // NC >= 2 always here (K >= 64)
    cpa_commit();

    int s = 0;
    for (int kc = 0; kc < NC; kc++) {
        cpa_wait<1>();       // chunk kc complete (1 group may remain in flight)
        __syncthreads();

        const uint32_t sAh = sb + s * STAGEB;
        const uint32_t sBh = sAh + MATB;
        const int lr = lane & 15;
        const int lc = (lane >> 4) * 16;

#pragma unroll
        for (int k16 = 0; k16 < 2; k16++) {
            const uint32_t kb = k16 * 32 + lc;
            uint32_t ah[4][4], bh[2][4];
#pragma unroll
            for (int i = 0; i < 4; i++)
                ldm_x4(ah[i], sAh + (uint32_t)(wm0 + i * 16 + lr) * PITCH + kb);
#pragma unroll
            for (int jj = 0; jj < 2; jj++)
                ldm_x4(bh[jj], sBh + (uint32_t)(wn0 + jj * 16 + lr) * PITCH + kb);
            if (k16 == 0) {
                const int pre = kc + 2;
                if (pre < NC) {
                    int ps = s + 2; if (ps >= 3) ps -= 3;
                    load_chunk(ps, pre);
                }
                cpa_commit();
            }
#pragma unroll
            for (int i = 0; i < 4; i++)
#pragma unroll
                for (int j = 0; j < 4; j++) {
                    const int jj = j >> 1, sel = j & 1;
                    mma16816(acc[i][j], ah[i], bh[jj][sel], bh[jj][sel + 2]);
                }
        }
        if (++s == 3) s = 0;
    }

    const int er = lane >> 2;
    const int ec = (lane & 3) * 2;
    float esum[4][2];
#pragma unroll
    for (int i = 0; i < 4; i++) { esum[i][0] = 0.0f; esum[i][1] = 0.0f; }

#pragma unroll
    for (int i = 0; i < 4; i++) {
#pragma unroll
        for (int j = 0; j < 4; j++) {
            const int col = col0 + wn0 + j * 8 + ec;
#pragma unroll
            for (int half_m = 0; half_m < 2; half_m++) {
                const int row = row0 + wm0 + i * 16 + er + half_m * 8;
                const float d0 = acc[i][j][half_m * 2 + 0];
                const float d1 = acc[i][j][half_m * 2 + 1];
                if (EPI == 2) {
                    float f0 = d0 + biasz[col];
                    float f1 = d1 + biasz[col + 1];
                    *(__half2*)(Ch + zC + (long long)row * N + col) =
                        __halves2half2(__float2half_rn(f0), __float2half_rn(f1));
                } else {
                    __half h0 = __float2half_rn(d0 * alpha);
                    __half h1 = __float2half_rn(d1 * alpha);
                    *(__half2*)(Ch + zC + (long long)row * N + col) = __halves2half2(h0, h1);
                    esum[i][half_m] += ex2(__half2float(h0) * L2E) + ex2(__half2float(h1) * L2E);
                }
            }
        }
    }

    if (EPI == 4) {
        __syncthreads();
        float* red = (float*)smem;   // [128][4]
#pragma unroll
        for (int i = 0; i < 4; i++) {
#pragma unroll
            for (int half_m = 0; half_m < 2; half_m++) {
                float v = esum[i][half_m];
                v += __shfl_xor_sync(0xffffffffu, v, 1);
                v += __shfl_xor_sync(0xffffffffu, v, 2);
                if ((lane & 3) == 0)
                    red[(wm0 + i * 16 + half_m * 8 + er) * 4 + wc] = v;
            }
        }
        __syncthreads();
        if (tid < 128) {
            float v = red[tid*4+0] + red[tid*4+1] + red[tid*4+2] + red[tid*4+3];
            atomicAdd(&rowsum[(long long)blockIdx.z * SS + row0 + tid], v);
        }
    }
}

// fused softmax+PV: out = (exp(S) @ V^T) / rowsum, 3-stage B pipeline
__global__ void __launch_bounds__(256, 2)
gemm_pv(const __half* __restrict__ Sc, const float* __restrict__ rowsum,
        const __half* __restrict__ Vt, float* __restrict__ out)
{
    extern __shared__ char smem[];
    const uint32_t sb = smem_u32(smem);
    const int tid = threadIdx.x;
    const int wid = tid >> 5, lane = tid & 31;
    const int wr = wid >> 2, wc = wid & 3;
    const int wm0 = wr * 64, wn0 = wc * 32;

    const int col0 = blockIdx.x << 7, row0 = blockIdx.y << 7, b = blockIdx.z;
    const __half* A  = Sc + ((long long)(b * SS + row0)) * SS;
    const __half* Bv = Vt + ((long long)(b * DD + col0)) * SS;
    float* C = out + ((long long)(b * SS + row0)) * DD;

    const int arow  = tid >> 1;
    const int acolh = (tid & 1) * 16;
    const int brow0 = tid >> 2, bu = tid & 3;

    auto load_b = [&](int stage, int kc) {
        const uint32_t d = sb + stage * STAGEB + MATB;
        const __half* g = Bv + kc * 32;
#pragma unroll
        for (int it = 0; it < 2; it++) {
            const int r = brow0 + it * 64;
            cpa16(d + r * PITCH + bu * 16, g + (long long)r * SS + bu * 8);
        }
    };

    uint4 areg0, areg1;
    {
        const __half* p = A + (long long)arow * SS + acolh;
        areg0 = *(const uint4*)p;
        areg1 = *(const uint4*)(p + 8);
        load_b(0, 0);
        cpa_commit();
        load_b(1, 1);
        cpa_commit();
    }

    float acc[4][4][4];
#pragma unroll
    for (int i = 0; i < 4; i++)
#pragma unroll
        for (int j = 0; j < 4; j++)
#pragma unroll
            for (int q = 0; q < 4; q++) acc[i][j][q] = 0.0f;

    const int NC = SS >> 5;

    int s = 0;
    for (int kc = 0; kc < NC; kc++) {
        // convert prefetched scores -> exp, STS into stage s A tile
        // (stage s A was read in iter kc-3; sync of iter kc-1 makes this safe)
        {
            char* d = smem + s * STAGEB + arow * PITCH + acolh * 2;
            __half2 o[8];
            const __half2* h2a = (const __half2*)&areg0;
            const __half2* h2b = (const __half2*)&areg1;
#pragma unroll
            for (int j = 0; j < 4; j++) {
                float2 f = __half22float2(h2a[j]);
                f.x = ex2(f.x * L2E);
                f.y = ex2(f.y * L2E);
                o[j] = __float22half2_rn(f);
            }
#pragma unroll
            for (int j = 0; j < 4; j++) {
                float2 f = __half22float2(h2b[j]);
                f.x = ex2(f.x * L2E);
                f.y = ex2(f.y * L2E);
                o[4 + j] = __float22half2_rn(f);
            }
            *(uint4*)d        = *(uint4*)&o[0];
            *(uint4*)(d + 16) = *(uint4*)&o[4];
        }
        cpa_wait<1>();
        __syncthreads();

        const uint32_t sA = sb + s * STAGEB;
        const uint32_t sB = sA + MATB;
        const int lr = lane & 15;
        const int lc = (lane >> 4) * 16;

#pragma unroll
        for (int k16 = 0; k16 < 2; k16++) {
            const uint32_t kb = k16 * 32 + lc;
            uint32_t ah[4][4], bh[2][4];
#pragma unroll
            for (int i = 0; i < 4; i++)
                ldm_x4(ah[i], sA + (uint32_t)(wm0 + i * 16 + lr) * PITCH + kb);
#pragma unroll
            for (int jj = 0; jj < 2; jj++)
                ldm_x4(bh[jj], sB + (uint32_t)(wn0 + jj * 16 + lr) * PITCH + kb);

            if (k16 == 0) {
                if (kc + 1 < NC) {
                    const __half* p = A + (long long)arow * SS + (kc + 1) * 32 + acolh;
                    areg0 = *(const uint4*)p;
                    areg1 = *(const uint4*)(p + 8);
                }
                const int pre = kc + 2;
                if (pre < NC) {
                    int ps = s + 2; if (ps >= 3) ps -= 3;
                    load_b(ps, pre);
                }
                cpa_commit();
            }
#pragma unroll
            for (int i = 0; i < 4; i++)
#pragma unroll
                for (int j = 0; j < 4; j++) {
                    const int jj = j >> 1, sel = j & 1;
                    mma16816(acc[i][j], ah[i], bh[jj][sel], bh[jj][sel + 2]);
                }
        }
        if (++s == 3) s = 0;
    }

    const int er = lane >> 2;
    const int ec = (lane & 3) * 2;
#pragma unroll
    for (int i = 0; i < 4; i++) {
#pragma unroll
        for (int half_m = 0; half_m < 2; half_m++) {
            const int lrow = wm0 + i * 16 + er + half_m * 8;
            const float inv = 1.0f / rowsum[b * SS + row0 + lrow];
#pragma unroll
            for (int j = 0; j < 4; j++) {
                const int col = col0 + wn0 + j * 8 + ec;
                float2 v;
                v.x = acc[i][j][half_m * 2 + 0] * inv;
                v.y = acc[i][j][half_m * 2 + 1] * inv;
                *(float2*)(C + (long long)lrow * DD + col) = v;
            }
        }
    }
}

__global__ void __launch_bounds__(256)
cvt_f32_f16(const float* __restrict__ s, __half* __restrict__ h, int n4)
{
    int i = blockIdx.x * 256 + threadIdx.x;
    if (i >= n4) return;
    float4 v = ((const float4*)s)[i];
    *(__half2*)(h + 4*i)     = __halves2half2(__float2half_rn(v.x), __float2half_rn(v.y));
    *(__half2*)(h + 4*i + 2) = __halves2half2(__float2half_rn(v.z), __float2half_rn(v.w));
}

// fp32 [R,C] -> fp16 [C,R]
__global__ void __launch_bounds__(256)
transpose_cvt(const float* __restrict__ src, __half* __restrict__ dst, int R, int C)
{
    __shared__ float t[32][33];
    const int c0 = blockIdx.x * 32, r0 = blockIdx.y * 32;
    const int tx = threadIdx.x, ty = threadIdx.y;
#pragma unroll
    for (int k = 0; k < 4; k++)
        t[ty + 8*k][tx] = src[(long long)(r0 + ty + 8*k) * C + c0 + tx];
    __syncthreads();
#pragma unroll
    for (int k = 0; k < 4; k++)
        dst[(long long)(c0 + ty + 8*k) * R + r0 + tx] = __float2half_rn(t[tx][ty + 8*k]);
}

// fp16 [R,C] -> fp16 [C,R] per batch
__global__ void __launch_bounds__(256)
transpose_h16(const __half* __restrict__ src, __half* __restrict__ dst,
              int R, int C, long long sS, long long sD)
{
    __shared__ __half t[32][34];
    const __half* S = src + (long long)blockIdx.z * sS;
    __half* D = dst + (long long)blockIdx.z * sD;
    const int c0 = blockIdx.x * 32, r0 = blockIdx.y * 32;
    const int tx = threadIdx.x, ty = threadIdx.y;
#pragma unroll
    for (int k = 0; k < 4; k++)
        t[ty + 8*k][tx] = S[(long long)(r0 + ty + 8*k) * C + c0 + tx];
    __syncthreads();
#pragma unroll
    for (int k = 0; k < 4; k++)
        D[(long long)(c0 + ty + 8*k) * R + r0 + tx] = t[tx][ty + 8*k];
}

extern "C" void kernel_launch(void* const* d_in, const int* in_sizes, int n_in,
                              void* d_out, int out_size)
{
    (void)in_sizes; (void)n_in; (void)out_size;
    const float* x  = (const float*)d_in[0];
    const float* Wq = (const float*)d_in[1];
    const float* bq = (const float*)d_in[2];
    const float* Wk = (const float*)d_in[3];
    const float* bk = (const float*)d_in[4];
    const float* Wv = (const float*)d_in[5];
    const float* bv = (const float*)d_in[6];
    float* out = (float*)d_out;

    __half *xh, *Wth, *QKV, *Vth, *Sc;
    float *bias, *rowsum;
    cudaGetSymbolAddress((void**)&xh,     g_xh);
    cudaGetSymbolAddress((void**)&Wth,    g_Wth);
    cudaGetSymbolAddress((void**)&bias,   g_bias);
    cudaGetSymbolAddress((void**)&QKV,    g_QKV);
    cudaGetSymbolAddress((void**)&Vth,    g_Vth);
    cudaGetSymbolAddress((void**)&Sc,     g_Sc);
    cudaGetSymbolAddress((void**)&rowsum, g_rowsum);

    cudaFuncSetAttribute((const void*)gemm_mma<2>, cudaFuncAttributeMaxDynamicSharedMemorySize, SMEM_G);
    cudaFuncSetAttribute((const void*)gemm_mma<4>, cudaFuncAttributeMaxDynamicSharedMemorySize, SMEM_G);
    cudaFuncSetAttribute((const void*)gemm_pv,     cudaFuncAttributeMaxDynamicSharedMemorySize, SMEM_G);

    const float scale = 1.0f / sqrtf((float)DD);
    __half* Qh = QKV + 0 * (long long)MTOT * DD;
    __half* Kh = QKV + 1 * (long long)MTOT * DD;
    __half* Vh = QKV + 2 * (long long)MTOT * DD;

    cudaMemcpyAsync(bias + 0*DD, bq, DD * sizeof(float), cudaMemcpyDeviceToDevice);
    cudaMemcpyAsync(bias + 1*DD, bk, DD * sizeof(float), cudaMemcpyDeviceToDevice);
    cudaMemcpyAsync(bias + 2*DD, bv, DD * sizeof(float), cudaMemcpyDeviceToDevice);

    {
        dim3 tb(32, 8), tg(DD/32, DD/32);
        transpose_cvt<<<tg, tb>>>(Wq, Wth + 0*DD*DD, DD, DD);
        transpose_cvt<<<tg, tb>>>(Wk, Wth + 1*DD*DD, DD, DD);
        transpose_cvt<<<tg, tb>>>(Wv, Wth + 2*DD*DD, DD, DD);
    }
    {
        int n4 = MTOT * DD / 4;
        cvt_f32_f16<<<(n4 + 255) / 256, 256>>>(x, xh, n4);
    }
    // merged Q/K/V projections: z = 0..2
    {
        dim3 g(DD/128, MTOT/128, 3);
        gemm_mma<2><<<g, 256, SMEM_G>>>(xh, Wth, bias, QKV, nullptr,
                                        DD, DD, 1.0f,
                                        0, (long long)DD*DD, (long long)MTOT*DD);
    }
    {
        dim3 tb(32, 8), tg(DD/32, SS/32, BB);
        transpose_h16<<<tg, tb>>>(Vh, Vth, SS, DD, (long long)SS*DD, (long long)DD*SS);
    }
    cudaMemsetAsync(rowsum, 0, MTOT * sizeof(float));
    {
        dim3 g(SS/128, SS/128, BB);
        gemm_mma<4><<<g, 256, SMEM_G>>>(Qh, Kh, nullptr, Sc, rowsum,
                                        SS, DD, scale,
                                        (long long)SS*DD, (long long)SS*DD,
                                        (long long)SS*SS);
    }
    {
        dim3 g(DD/128, SS/128, BB);
        gemm_pv<<<g, 256, SMEM_G>>>(Sc, rowsum, Vth, out);
    }
}

// round 16
// speedup vs baseline: 1.3060x; 1.1024x over previous
#include <cuda_runtime.h>
#include <cuda_fp16.h>
#include <math.h>
#include <stdint.h>

#define BB 8
#define SS 2048
#define DD 512
#define MTOT (BB*SS)

__device__ __half g_xh[MTOT*DD];
__device__ __half g_Wth[3][DD*DD];
__device__ float  g_bias[3*DD];
__device__ __half g_QKV[3][MTOT*DD];
__device__ __half g_Vth[MTOT*DD];
__device__ __half g_P[(long long)BB*SS*SS];      // exp(scores), fp16
__device__ float  g_rowsum[MTOT];

__device__ __forceinline__ uint32_t smem_u32(const void* p){
    uint32_t a;
    asm("{ .reg .u64 t; cvta.to.shared.u64 t, %1; cvt.u32.u64 %0, t; }" : "=r"(a) : "l"(p));
    return a;
}
__device__ __forceinline__ void cpa16(uint32_t dst, const void* src){
    asm volatile("cp.async.cg.shared.global [%0], [%1], 16;" :: "r"(dst), "l"(src));
}
__device__ __forceinline__ void cpa_commit(){ asm volatile("cp.async.commit_group;"); }
template<int N> __device__ __forceinline__ void cpa_wait(){
    asm volatile("cp.async.wait_group %0;" :: "n"(N));
}
__device__ __forceinline__ void ldm_x4(uint32_t* r, uint32_t addr){
    asm volatile("ldmatrix.sync.aligned.m8n8.x4.shared.b16 {%0,%1,%2,%3}, [%4];"
        : "=r"(r[0]), "=r"(r[1]), "=r"(r[2]), "=r"(r[3]) : "r"(addr));
}
__device__ __forceinline__ void mma16816(float* d, const uint32_t* a, uint32_t b0, uint32_t b1){
    asm volatile("mma.sync.aligned.m16n8k16.row.col.f32.f16.f16.f32 "
        "{%0,%1,%2,%3},{%4,%5,%6,%7},{%8,%9},{%0,%1,%2,%3};"
        : "+f"(d[0]), "+f"(d[1]), "+f"(d[2]), "+f"(d[3])
        : "r"(a[0]), "r"(a[1]), "r"(a[2]), "r"(a[3]), "r"(b0), "r"(b1));
}
__device__ __forceinline__ float ex2(float x){
    float r;
    asm("ex2.approx.ftz.f32 %0, %1;" : "=f"(r) : "f"(x));
    return r;
}
#define L2E 1.44269504f

#define PITCH   80
#define MATB    (128*PITCH)
#define STAGEB  (2*MATB)        // A + B per stage
#define SMEM_G  (3*STAGEB)      // 61440, 3-stage

// 256 threads, 8 warps of 64x32, CTA tile 128x128, K-chunk 32, 3-stage, single sync.
// C = A * B^T, plain fp16 operands.
// EPI 2: Ch = fp16(D + bias[z])
// EPI 4: Ch = fp16(ex2(alpha*D)); per-row sum of stored values atomicAdd'ed to rowsum
// EPI 5: Cf = D / rowsum[z*SS + row]   (fp32 out)
template<int EPI>
__global__ void __launch_bounds__(256, 2)
gemm_mma(const __half* __restrict__ Ah, const __half* __restrict__ Bh,
         const float* __restrict__ bias,
         __half* __restrict__ Ch, float* __restrict__ Cf, float* __restrict__ rowsum,
         int N, int K, float alpha,
         long long sA, long long sB, long long sC)
{
    extern __shared__ char smem[];
    const uint32_t sb = smem_u32(smem);
    const int tid = threadIdx.x;
    const int wid = tid >> 5, lane = tid & 31;
    const int wr = wid >> 2, wc = wid & 3;
    const int wm0 = wr * 64, wn0 = wc * 32;

    const int row0 = blockIdx.y << 7, col0 = blockIdx.x << 7;
    const long long zA = (long long)blockIdx.z * sA;
    const long long zB = (long long)blockIdx.z * sB;
    const long long zC = (long long)blockIdx.z * sC;
    const float* biasz = (EPI == 2) ? (bias + blockIdx.z * DD) : bias;

    const __half* gsrc[2] = { Ah + zA + (long long)row0 * K,
                              Bh + zB + (long long)col0 * K };

    const int lrow0 = tid >> 2;
    const int lu    = tid & 3;

    float acc[4][4][4];
#pragma unroll
    for (int i = 0; i < 4; i++)
#pragma unroll
        for (int j = 0; j < 4; j++)
#pragma unroll
            for (int q = 0; q < 4; q++) acc[i][j][q] = 0.0f;

    const int NC = K >> 5;

    auto load_chunk = [&](int stage, int kc) {
        const uint32_t sdst = sb + stage * STAGEB;
#pragma unroll
        for (int m = 0; m < 2; m++) {
            const __half* g = gsrc[m] + kc * 32;
#pragma unroll
            for (int it = 0; it < 2; it++) {
                const int row = lrow0 + it * 64;
                cpa16(sdst + m * MATB + row * PITCH + lu * 16,
                      g + (long long)row * K + lu * 8);
            }
        }
    };

    load_chunk(0, 0);
    cpa_commit();
    load_chunk(1, 1);
    cpa_commit();

    int s = 0;
    for (int kc = 0; kc < NC; kc++) {
        cpa_wait<1>();
        __syncthreads();

        const uint32_t sAh = sb + s * STAGEB;
        const uint32_t sBh = sAh + MATB;
        const int lr = lane & 15;
        const int lc = (lane >> 4) * 16;

#pragma unroll
        for (int k16 = 0; k16 < 2; k16++) {
            const uint32_t kb = k16 * 32 + lc;
            uint32_t ah[4][4], bh[2][4];
#pragma unroll
            for (int i = 0; i < 4; i++)
                ldm_x4(ah[i], sAh + (uint32_t)(wm0 + i * 16 + lr) * PITCH + kb);
#pragma unroll
            for (int jj = 0; jj < 2; jj++)
                ldm_x4(bh[jj], sBh + (uint32_t)(wn0 + jj * 16 + lr) * PITCH + kb);
            if (k16 == 0) {
                const int pre = kc + 2;
                if (pre < NC) {
                    int ps = s + 2; if (ps >= 3) ps -= 3;
                    load_chunk(ps, pre);
                }
                cpa_commit();
            }
#pragma unroll
            for (int i = 0; i < 4; i++)
#pragma unroll
                for (int j = 0; j < 4; j++) {
                    const int jj = j >> 1, sel = j & 1;
                    mma16816(acc[i][j], ah[i], bh[jj][sel], bh[jj][sel + 2]);
                }
        }
        if (++s == 3) s = 0;
    }

    const int er = lane >> 2;
    const int ec = (lane & 3) * 2;
    float esum[4][2];
#pragma unroll
    for (int i = 0; i < 4; i++) { esum[i][0] = 0.0f; esum[i][1] = 0.0f; }

#pragma unroll
    for (int i = 0; i < 4; i++) {
#pragma unroll
        for (int j = 0; j < 4; j++) {
            const int col = col0 + wn0 + j * 8 + ec;
#pragma unroll
            for (int half_m = 0; half_m < 2; half_m++) {
                const int row = row0 + wm0 + i * 16 + er + half_m * 8;
                const float d0 = acc[i][j][half_m * 2 + 0];
                const float d1 = acc[i][j][half_m * 2 + 1];
                if (EPI == 2) {
                    float f0 = d0 + biasz[col];
                    float f1 = d1 + biasz[col + 1];
                    *(__half2*)(Ch + zC + (long long)row * N + col) =
                        __halves2half2(__float2half_rn(f0), __float2half_rn(f1));
                } else if (EPI == 4) {
                    __half h0 = __float2half_rn(ex2(d0 * alpha));
                    __half h1 = __float2half_rn(ex2(d1 * alpha));
                    *(__half2*)(Ch + zC + (long long)row * N + col) = __halves2half2(h0, h1);
                    esum[i][half_m] += __half2float(h0) + __half2float(h1);
                } else {
                    const float inv = 1.0f /
                        rowsum[(long long)blockIdx.z * SS + row];
                    float2 v;
                    v.x = d0 * inv; v.y = d1 * inv;
                    *(float2*)(Cf + zC + (long long)row * N + col) = v;
                }
            }
        }
    }

    if (EPI == 4) {
        __syncthreads();
        float* red = (float*)smem;   // [128][4]
#pragma unroll
        for (int i = 0; i < 4; i++) {
#pragma unroll
            for (int half_m = 0; half_m < 2; half_m++) {
                float v = esum[i][half_m];
                v += __shfl_xor_sync(0xffffffffu, v, 1);
                v += __shfl_xor_sync(0xffffffffu, v, 2);
                if ((lane & 3) == 0)
                    red[(wm0 + i * 16 + half_m * 8 + er) * 4 + wc] = v;
            }
        }
        __syncthreads();
        if (tid < 128) {
            float v = red[tid*4+0] + red[tid*4+1] + red[tid*4+2] + red[tid*4+3];
            atomicAdd(&rowsum[(long long)blockIdx.z * SS + row0 + tid], v);
        }
    }
}

__global__ void __launch_bounds__(256)
cvt_f32_f16(const float* __restrict__ s, __half* __restrict__ h, int n4)
{
    int i = blockIdx.x * 256 + threadIdx.x;
    if (i >= n4) return;
    float4 v = ((const float4*)s)[i];
    *(__half2*)(h + 4*i)     = __halves2half2(__float2half_rn(v.x), __float2half_rn(v.y));
    *(__half2*)(h + 4*i + 2) = __halves2half2(__float2half_rn(v.z), __float2half_rn(v.w));
}

// fp32 [R,C] -> fp16 [C,R]
__global__ void __launch_bounds__(256)
transpose_cvt(const float* __restrict__ src, __half* __restrict__ dst, int R, int C)
{
    __shared__ float t[32][33];
    const int c0 = blockIdx.x * 32, r0 = blockIdx.y * 32;
    const int tx = threadIdx.x, ty = threadIdx.y;
#pragma unroll
    for (int k = 0; k < 4; k++)
        t[ty + 8*k][tx] = src[(long long)(r0 + ty + 8*k) * C + c0 + tx];
    __syncthreads();
#pragma unroll
    for (int k = 0; k < 4; k++)
        dst[(long long)(c0 + ty + 8*k) * R + r0 + tx] = __float2half_rn(t[tx][ty + 8*k]);
}

// fp16 [R,C] -> fp16 [C,R] per batch
__global__ void __launch_bounds__(256)
transpose_h16(const __half* __restrict__ src, __half* __restrict__ dst,
              int R, int C, long long sS, long long sD)
{
    __shared__ __half t[32][34];
    const __half* S = src + (long long)blockIdx.z * sS;
    __half* D = dst + (long long)blockIdx.z * sD;
    const int c0 = blockIdx.x * 32, r0 = blockIdx.y * 32;
    const int tx = threadIdx.x, ty = threadIdx.y;
#pragma unroll
    for (int k = 0; k < 4; k++)
        t[ty + 8*k][tx] = S[(long long)(r0 + ty + 8*k) * C + c0 + tx];
    __syncthreads();
#pragma unroll
    for (int k = 0; k < 4; k++)
        D[(long long)(c0 + ty + 8*k) * R + r0 + tx] = t[tx][ty + 8*k];
}

extern "C" void kernel_launch(void* const* d_in, const int* in_sizes, int n_in,
                              void* d_out, int out_size)
{
    (void)in_sizes; (void)n_in; (void)out_size;
    const float* x  = (const float*)d_in[0];
    const float* Wq = (const float*)d_in[1];
    const float* bq = (const float*)d_in[2];
    const float* Wk = (const float*)d_in[3];
    const float* bk = (const float*)d_in[4];
    const float* Wv = (const float*)d_in[5];
    const float* bv = (const float*)d_in[6];
    float* out = (float*)d_out;

    __half *xh, *Wth, *QKV, *Vth, *P;
    float *bias, *rowsum;
    cudaGetSymbolAddress((void**)&xh,     g_xh);
    cudaGetSymbolAddress((void**)&Wth,    g_Wth);
    cudaGetSymbolAddress((void**)&bias,   g_bias);
    cudaGetSymbolAddress((void**)&QKV,    g_QKV);
    cudaGetSymbolAddress((void**)&Vth,    g_Vth);
    cudaGetSymbolAddress((void**)&P,      g_P);
    cudaGetSymbolAddress((void**)&rowsum, g_rowsum);

    cudaFuncSetAttribute((const void*)gemm_mma<2>, cudaFuncAttributeMaxDynamicSharedMemorySize, SMEM_G);
    cudaFuncSetAttribute((const void*)gemm_mma<4>, cudaFuncAttributeMaxDynamicSharedMemorySize, SMEM_G);
    cudaFuncSetAttribute((const void*)gemm_mma<5>, cudaFuncAttributeMaxDynamicSharedMemorySize, SMEM_G);

    const float scale = 1.0f / sqrtf((float)DD);
    __half* Qh = QKV + 0 * (long long)MTOT * DD;
    __half* Kh = QKV + 1 * (long long)MTOT * DD;
    __half* Vh = QKV + 2 * (long long)MTOT * DD;

    cudaMemcpyAsync(bias + 0*DD, bq, DD * sizeof(float), cudaMemcpyDeviceToDevice);
    cudaMemcpyAsync(bias + 1*DD, bk, DD * sizeof(float), cudaMemcpyDeviceToDevice);
    cudaMemcpyAsync(bias + 2*DD, bv, DD * sizeof(float), cudaMemcpyDeviceToDevice);

    {
        dim3 tb(32, 8), tg(DD/32, DD/32);
        transpose_cvt<<<tg, tb>>>(Wq, Wth + 0*DD*DD, DD, DD);
        transpose_cvt<<<tg, tb>>>(Wk, Wth + 1*DD*DD, DD, DD);
        transpose_cvt<<<tg, tb>>>(Wv, Wth + 2*DD*DD, DD, DD);
    }
    {
        int n4 = MTOT * DD / 4;
        cvt_f32_f16<<<(n4 + 255) / 256, 256>>>(x, xh, n4);
    }
    // merged Q/K/V projections: z = 0..2
    {
        dim3 g(DD/128, MTOT/128, 3);
        gemm_mma<2><<<g, 256, SMEM_G>>>(xh, Wth, bias, QKV, nullptr, nullptr,
                                        DD, DD, 1.0f,
                                        0, (long long)DD*DD, (long long)MTOT*DD);
    }
    {
        dim3 tb(32, 8), tg(DD/32, SS/32, BB);
        transpose_h16<<<tg, tb>>>(Vh, Vth, SS, DD, (long long)SS*DD, (long long)DD*SS);
    }
    cudaMemsetAsync(rowsum, 0, MTOT * sizeof(float));
    // P = exp(scale * Q K^T), rowsum accumulated (alpha premultiplied by log2 e)
    {
        dim3 g(SS/128, SS/128, BB);
        gemm_mma<4><<<g, 256, SMEM_G>>>(Qh, Kh, nullptr, P, nullptr, rowsum,
                                        SS, DD, scale * L2E,
                                        (long long)SS*DD, (long long)SS*DD,
                                        (long long)SS*SS);
    }
    // out = (P @ V^T) / rowsum  -- pure GEMM, cp.async both operands
    {
        dim3 g(DD/128, SS/128, BB);
        gemm_mma<5><<<g, 256, SMEM_G>>>(P, Vth, nullptr, nullptr, out, rowsum,
                                        DD, SS, 1.0f,
                                        (long long)SS*SS, (long long)DD*SS,
                                        (long long)SS*DD);
    }
}